// round 5
// baseline (speedup 1.0000x reference)
#include <cuda_runtime.h>

#define N_NODES 100000
#define E_EDGES 1600000
#define DIM 128
#define NV4 (N_NODES * 32)   // number of float4 per feature matrix

// Scratch (static device globals — allowed; zero-initialized at module load)
__device__ float d_g[N_NODES * DIM];      // dis[src]-scaled projection
__device__ float d_accum[N_NODES * DIM];  // scatter accumulator (kept zeroed between calls)
__device__ float d_xbuf[N_NODES * DIM];   // inter-layer activations
__device__ int   d_deg[N_NODES];
__device__ float d_dis[N_NODES];
__device__ int2  d_edges[E_EDGES];        // packed (src, dst) int32
__device__ int   d_is64;                  // edge_index dtype flag

// ---------------------------------------------------------------------------
// Dtype sniff: for int64 (little-endian, values < 2^31) every odd 32-bit word
// is zero; for int32 the odd words are random node indices. Sample 256 words
// from each half (src row + dst row) of the buffer.
// ---------------------------------------------------------------------------
__global__ void detect_kernel(const int* __restrict__ w) {
    __shared__ int any;
    if (threadIdx.x == 0) any = 0;
    __syncthreads();
    int bad = 0;
    if (w[2 * threadIdx.x + 1] != 0) bad = 1;                 // head of buffer
    if (w[2 * (E_EDGES + threadIdx.x) + 1] != 0) bad = 1;     // second half (if int64)
    if (bad) atomicOr(&any, 1);
    __syncthreads();
    if (threadIdx.x == 0) d_is64 = (any == 0) ? 1 : 0;
}

// ---------------------------------------------------------------------------
// Edge index conversion: (2,E) int64 OR int32 -> packed int2 (src,dst)
// Indices clamped to valid range (misinterpretation -> rel_err, not crash).
// ---------------------------------------------------------------------------
__global__ __launch_bounds__(256) void edge_convert_kernel(
        const void* __restrict__ eidx_raw) {
    int e = blockIdx.x * blockDim.x + threadIdx.x;
    if (e >= E_EDGES) return;
    int s, d;
    if (d_is64) {
        const long long* p = (const long long*)eidx_raw;
        s = (int)p[e];
        d = (int)p[E_EDGES + e];
    } else {
        const int* p = (const int*)eidx_raw;
        s = p[e];
        d = p[E_EDGES + e];
    }
    s = min(max(s, 0), N_NODES - 1);
    d = min(max(d, 0), N_NODES - 1);
    d_edges[e] = make_int2(s, d);
}

// ---------------------------------------------------------------------------
// Degree / normalization
// ---------------------------------------------------------------------------
__global__ __launch_bounds__(256) void deg_init_kernel() {
    int i = blockIdx.x * blockDim.x + threadIdx.x;
    if (i < N_NODES) d_deg[i] = 1;  // self loop
}

__global__ __launch_bounds__(256) void deg_count_kernel() {
    int e = blockIdx.x * blockDim.x + threadIdx.x;
    if (e < E_EDGES) atomicAdd(&d_deg[d_edges[e].x], 1);
}

__global__ __launch_bounds__(256) void dis_kernel() {
    int i = blockIdx.x * blockDim.x + threadIdx.x;
    if (i < N_NODES) d_dis[i] = rsqrtf((float)d_deg[i]);
}

// ---------------------------------------------------------------------------
// Projection: g[i,:] = dis[i] * (x[i,:] @ W^T + b)
// Block: 256 threads, 32 rows per block, full 128 cols, K tiled in 2 halves
// so static shared stays under 48 KB. Each thread: 4x4 register tile.
// ---------------------------------------------------------------------------
#define KT 64
#define WS_STRIDE 132
#define XS_STRIDE 36

__global__ __launch_bounds__(256) void linear_kernel(
        const float* __restrict__ x,
        const float* __restrict__ W,
        const float* __restrict__ bias,
        float* __restrict__ g) {
    __shared__ float wsT[KT * WS_STRIDE];  // [64][132] = 33.8 KB
    __shared__ float xsT[KT * XS_STRIDE];  // [64][36]  =  9.2 KB

    const int tid = threadIdx.x;          // 0..255
    const int row0 = blockIdx.x * 32;

    const int tc = tid & 31;   // col group: cols [4*tc, 4*tc+3]
    const int tr = tid >> 5;   // row group: rows [4*tr, 4*tr+3]

    float acc[4][4];
#pragma unroll
    for (int i = 0; i < 4; i++)
#pragma unroll
        for (int j = 0; j < 4; j++) acc[i][j] = 0.0f;

    for (int kt = 0; kt < 2; kt++) {
        const int k0 = kt * KT;

        // Load W half (128 rows x 64 k), W row-major W[n][k], transposed into wsT[k][n]
        for (int f = tid; f < DIM * KT / 4; f += 256) {
            int n = f >> 4;            // 16 float4 per half-row
            int kq = f & 15;
            float4 v = *(const float4*)&W[n * DIM + k0 + 4 * kq];
            int k = 4 * kq;
            wsT[(k + 0) * WS_STRIDE + n] = v.x;
            wsT[(k + 1) * WS_STRIDE + n] = v.y;
            wsT[(k + 2) * WS_STRIDE + n] = v.z;
            wsT[(k + 3) * WS_STRIDE + n] = v.w;
        }
        // Load x tile half (32 rows x 64 k) transposed into xsT[k][r]
        for (int f = tid; f < 32 * KT / 4; f += 256) {
            int r = f >> 4;
            int kq = f & 15;
            float4 v = *(const float4*)&x[(row0 + r) * DIM + k0 + 4 * kq];
            int k = 4 * kq;
            xsT[(k + 0) * XS_STRIDE + r] = v.x;
            xsT[(k + 1) * XS_STRIDE + r] = v.y;
            xsT[(k + 2) * XS_STRIDE + r] = v.z;
            xsT[(k + 3) * XS_STRIDE + r] = v.w;
        }
        __syncthreads();

        const float* wp = wsT + 4 * tc;
        const float* xp = xsT + 4 * tr;

#pragma unroll 8
        for (int k = 0; k < KT; k++) {
            float4 wv = *(const float4*)(wp + k * WS_STRIDE);
            float4 xv = *(const float4*)(xp + k * XS_STRIDE);
            acc[0][0] += xv.x * wv.x; acc[0][1] += xv.x * wv.y;
            acc[0][2] += xv.x * wv.z; acc[0][3] += xv.x * wv.w;
            acc[1][0] += xv.y * wv.x; acc[1][1] += xv.y * wv.y;
            acc[1][2] += xv.y * wv.z; acc[1][3] += xv.y * wv.w;
            acc[2][0] += xv.z * wv.x; acc[2][1] += xv.z * wv.y;
            acc[2][2] += xv.z * wv.z; acc[2][3] += xv.z * wv.w;
            acc[3][0] += xv.w * wv.x; acc[3][1] += xv.w * wv.y;
            acc[3][2] += xv.w * wv.z; acc[3][3] += xv.w * wv.w;
        }
        __syncthreads();
    }

    float4 bv = *(const float4*)&bias[4 * tc];
#pragma unroll
    for (int i = 0; i < 4; i++) {
        int row = row0 + 4 * tr + i;
        float s = d_dis[row];
        float4 o;
        o.x = s * (acc[i][0] + bv.x);
        o.y = s * (acc[i][1] + bv.y);
        o.z = s * (acc[i][2] + bv.z);
        o.w = s * (acc[i][3] + bv.w);
        *(float4*)&g[row * DIM + 4 * tc] = o;
    }
}

// ---------------------------------------------------------------------------
// Edge scatter: accum[dst,:] += g[src,:]  (one warp per edge, float4 per lane)
// Grid sized exactly: E_EDGES/8 blocks * 8 warps = E_EDGES warps, no guard.
// ---------------------------------------------------------------------------
__device__ __forceinline__ void red_add_v4(float4* addr, float4 v) {
    asm volatile("red.global.add.v4.f32 [%0], {%1, %2, %3, %4};"
                 :: "l"(addr), "f"(v.x), "f"(v.y), "f"(v.z), "f"(v.w)
                 : "memory");
}

__global__ __launch_bounds__(256) void edge_kernel() {
    int warp = (blockIdx.x * blockDim.x + threadIdx.x) >> 5;
    int lane = threadIdx.x & 31;
    int2 e = __ldg(&d_edges[warp]);   // warp-uniform 8B load + broadcast
    const float4* g4 = (const float4*)d_g;
    float4* a4 = (float4*)d_accum;
    float4 v = __ldg(&g4[e.x * 32 + lane]);
    red_add_v4(&a4[e.y * 32 + lane], v);
}

// ---------------------------------------------------------------------------
// Combine: out[i,:] = relu(dis[i] * (accum[i,:] + g[i,:])); re-zero accum
// (self-loop term dis[i]^2*h[i] == dis[i]*g[i] folded in here)
// ---------------------------------------------------------------------------
__global__ __launch_bounds__(256) void combine_kernel(float* __restrict__ out) {
    int idx = blockIdx.x * blockDim.x + threadIdx.x;
    if (idx >= NV4) return;
    int node = idx >> 5;  // 32 float4 per node; uniform across warp
    float s = d_dis[node];
    float4* a4 = (float4*)d_accum;
    const float4* g4 = (const float4*)d_g;
    float4 a = a4[idx];
    float4 gg = g4[idx];
    float4 r;
    r.x = fmaxf(s * (a.x + gg.x), 0.0f);
    r.y = fmaxf(s * (a.y + gg.y), 0.0f);
    r.z = fmaxf(s * (a.z + gg.z), 0.0f);
    r.w = fmaxf(s * (a.w + gg.w), 0.0f);
    ((float4*)out)[idx] = r;
    a4[idx] = make_float4(0.0f, 0.0f, 0.0f, 0.0f);
}

// ---------------------------------------------------------------------------
extern "C" void kernel_launch(void* const* d_in, const int* in_sizes, int n_in,
                              void* d_out, int out_size) {
    const float* x  = (const float*)d_in[0];
    const void*  eidx = d_in[1];  // (2, E) int64 OR int32 — sniffed on device
    const float* W1 = (const float*)d_in[2];
    const float* b1 = (const float*)d_in[3];
    const float* W2 = (const float*)d_in[4];
    const float* b2 = (const float*)d_in[5];
    const float* W3 = (const float*)d_in[6];
    const float* b3 = (const float*)d_in[7];
    float* out = (float*)d_out;

    // One-shot per call: sniff dtype, pack indices, compute degrees + dis
    detect_kernel<<<1, 256>>>((const int*)eidx);
    edge_convert_kernel<<<(E_EDGES + 255) / 256, 256>>>(eidx);
    deg_init_kernel<<<(N_NODES + 255) / 256, 256>>>();
    deg_count_kernel<<<(E_EDGES + 255) / 256, 256>>>();
    dis_kernel<<<(N_NODES + 255) / 256, 256>>>();

    float* g;     cudaGetSymbolAddress((void**)&g, d_g);
    float* xbuf;  cudaGetSymbolAddress((void**)&xbuf, d_xbuf);

    const int lin_grid = N_NODES / 32;            // 3125
    const int edge_blocks = E_EDGES / 8;          // warp per edge, 8 warps/block
    const int comb_blocks = (NV4 + 255) / 256;

    // Layer 1: x -> xbuf
    linear_kernel<<<lin_grid, 256>>>(x, W1, b1, g);
    edge_kernel<<<edge_blocks, 256>>>();
    combine_kernel<<<comb_blocks, 256>>>(xbuf);

    // Layer 2: xbuf -> xbuf
    linear_kernel<<<lin_grid, 256>>>(xbuf, W2, b2, g);
    edge_kernel<<<edge_blocks, 256>>>();
    combine_kernel<<<comb_blocks, 256>>>(xbuf);

    // Layer 3: xbuf -> out
    linear_kernel<<<lin_grid, 256>>>(xbuf, W3, b3, g);
    edge_kernel<<<edge_blocks, 256>>>();
    combine_kernel<<<comb_blocks, 256>>>(out);
}

// round 7
// speedup vs baseline: 1.1146x; 1.1146x over previous
#include <cuda_runtime.h>

#define N_NODES 100000
#define E_EDGES 1600000
#define DIM 128
#define NV4 (N_NODES * 32)
#define SCAN_BLOCKS 391   // ceil(100000/256)

// Scratch (static device globals; zero-initialized at load)
__device__ float d_g[N_NODES * DIM];      // dis[src]-scaled projection
__device__ float d_xbuf[N_NODES * DIM];   // inter-layer activations
__device__ int   d_deg_src[N_NODES];
__device__ int   d_deg_dst[N_NODES];
__device__ float d_dis[N_NODES];
__device__ int2  d_edges[E_EDGES];        // packed (src, dst) int32
__device__ int   d_is64;
__device__ int   d_rowptr[N_NODES + 1];
__device__ int   d_rowtmp[N_NODES];
__device__ int   d_cursor[N_NODES];
__device__ int   d_csr_src[E_EDGES];
__device__ int   d_blocksum[512];
__device__ int   d_blockoff[512];

// ---------------------------------------------------------------------------
// Dtype sniff: int64 (values < 2^31, LE) -> every odd 32-bit word is zero.
// ---------------------------------------------------------------------------
__global__ void detect_kernel(const int* __restrict__ w) {
    __shared__ int any;
    if (threadIdx.x == 0) any = 0;
    __syncthreads();
    int bad = 0;
    if (w[2 * threadIdx.x + 1] != 0) bad = 1;
    if (w[2 * (E_EDGES + threadIdx.x) + 1] != 0) bad = 1;
    if (bad) atomicOr(&any, 1);
    __syncthreads();
    if (threadIdx.x == 0) d_is64 = (any == 0) ? 1 : 0;
}

// ---------------------------------------------------------------------------
// Edge conversion: (2,E) int64 OR int32 -> packed int2 (src,dst), clamped.
// ---------------------------------------------------------------------------
__global__ __launch_bounds__(256) void edge_convert_kernel(
        const void* __restrict__ eidx_raw) {
    int e = blockIdx.x * blockDim.x + threadIdx.x;
    if (e >= E_EDGES) return;
    int s, d;
    if (d_is64) {
        const long long* p = (const long long*)eidx_raw;
        s = (int)p[e];
        d = (int)p[E_EDGES + e];
    } else {
        const int* p = (const int*)eidx_raw;
        s = p[e];
        d = p[E_EDGES + e];
    }
    s = min(max(s, 0), N_NODES - 1);
    d = min(max(d, 0), N_NODES - 1);
    d_edges[e] = make_int2(s, d);
}

// ---------------------------------------------------------------------------
// Degree counting (both directions), zeroed first.
// ---------------------------------------------------------------------------
__global__ __launch_bounds__(256) void deg_zero_kernel() {
    int i = blockIdx.x * blockDim.x + threadIdx.x;
    if (i < N_NODES) { d_deg_src[i] = 0; d_deg_dst[i] = 0; }
}

__global__ __launch_bounds__(256) void deg_count_kernel() {
    int e = blockIdx.x * blockDim.x + threadIdx.x;
    if (e >= E_EDGES) return;
    int2 p = d_edges[e];
    atomicAdd(&d_deg_src[p.x], 1);
    atomicAdd(&d_deg_dst[p.y], 1);
}

// ---------------------------------------------------------------------------
// 3-phase exclusive scan of d_deg_dst -> d_rowptr (+ cursor + dis)
// ---------------------------------------------------------------------------
__global__ __launch_bounds__(256) void scan1_kernel() {
    __shared__ int s[256];
    int t = threadIdx.x;
    int i = blockIdx.x * 256 + t;
    int v = (i < N_NODES) ? d_deg_dst[i] : 0;
    s[t] = v;
    __syncthreads();
#pragma unroll
    for (int off = 1; off < 256; off <<= 1) {
        int add = (t >= off) ? s[t - off] : 0;
        __syncthreads();
        s[t] += add;
        __syncthreads();
    }
    if (i < N_NODES) d_rowtmp[i] = s[t] - v;       // exclusive within block
    if (t == 255) d_blocksum[blockIdx.x] = s[255]; // block total
}

__global__ void scan2_kernel() {
    __shared__ int s[512];
    int t = threadIdx.x;
    int v = (t < SCAN_BLOCKS) ? d_blocksum[t] : 0;
    s[t] = v;
    __syncthreads();
#pragma unroll
    for (int off = 1; off < 512; off <<= 1) {
        int add = (t >= off) ? s[t - off] : 0;
        __syncthreads();
        s[t] += add;
        __syncthreads();
    }
    d_blockoff[t] = s[t] - v;  // exclusive
}

__global__ __launch_bounds__(256) void scan3_kernel() {
    int i = blockIdx.x * 256 + threadIdx.x;
    if (i >= N_NODES) return;
    int r = d_rowtmp[i] + d_blockoff[blockIdx.x];
    d_rowptr[i] = r;
    d_cursor[i] = r;
    d_dis[i] = rsqrtf((float)(d_deg_src[i] + 1));  // +1 self loop
    if (i == 0) d_rowptr[N_NODES] = E_EDGES;
}

// ---------------------------------------------------------------------------
// CSR scatter: bucket src indices by dst.
// ---------------------------------------------------------------------------
__global__ __launch_bounds__(256) void scatter_kernel() {
    int e = blockIdx.x * blockDim.x + threadIdx.x;
    if (e >= E_EDGES) return;
    int2 p = d_edges[e];
    int pos = atomicAdd(&d_cursor[p.y], 1);
    d_csr_src[pos] = p.x;
}

// ---------------------------------------------------------------------------
// Projection: g[i,:] = dis[i] * (x[i,:] @ W^T + b)
// ---------------------------------------------------------------------------
#define KT 64
#define WS_STRIDE 132
#define XS_STRIDE 36

__global__ __launch_bounds__(256) void linear_kernel(
        const float* __restrict__ x,
        const float* __restrict__ W,
        const float* __restrict__ bias,
        float* __restrict__ g) {
    __shared__ float wsT[KT * WS_STRIDE];  // [64][132]
    __shared__ float xsT[KT * XS_STRIDE];  // [64][36]

    const int tid = threadIdx.x;
    const int row0 = blockIdx.x * 32;
    const int tc = tid & 31;
    const int tr = tid >> 5;

    float acc[4][4];
#pragma unroll
    for (int i = 0; i < 4; i++)
#pragma unroll
        for (int j = 0; j < 4; j++) acc[i][j] = 0.0f;

    for (int kt = 0; kt < 2; kt++) {
        const int k0 = kt * KT;
        for (int f = tid; f < DIM * KT / 4; f += 256) {
            int n = f >> 4;
            int kq = f & 15;
            float4 v = *(const float4*)&W[n * DIM + k0 + 4 * kq];
            int k = 4 * kq;
            wsT[(k + 0) * WS_STRIDE + n] = v.x;
            wsT[(k + 1) * WS_STRIDE + n] = v.y;
            wsT[(k + 2) * WS_STRIDE + n] = v.z;
            wsT[(k + 3) * WS_STRIDE + n] = v.w;
        }
        for (int f = tid; f < 32 * KT / 4; f += 256) {
            int r = f >> 4;
            int kq = f & 15;
            float4 v = *(const float4*)&x[(row0 + r) * DIM + k0 + 4 * kq];
            int k = 4 * kq;
            xsT[(k + 0) * XS_STRIDE + r] = v.x;
            xsT[(k + 1) * XS_STRIDE + r] = v.y;
            xsT[(k + 2) * XS_STRIDE + r] = v.z;
            xsT[(k + 3) * XS_STRIDE + r] = v.w;
        }
        __syncthreads();

        const float* wp = wsT + 4 * tc;
        const float* xp = xsT + 4 * tr;
#pragma unroll 8
        for (int k = 0; k < KT; k++) {
            float4 wv = *(const float4*)(wp + k * WS_STRIDE);
            float4 xv = *(const float4*)(xp + k * XS_STRIDE);
            acc[0][0] += xv.x * wv.x; acc[0][1] += xv.x * wv.y;
            acc[0][2] += xv.x * wv.z; acc[0][3] += xv.x * wv.w;
            acc[1][0] += xv.y * wv.x; acc[1][1] += xv.y * wv.y;
            acc[1][2] += xv.y * wv.z; acc[1][3] += xv.y * wv.w;
            acc[2][0] += xv.z * wv.x; acc[2][1] += xv.z * wv.y;
            acc[2][2] += xv.z * wv.z; acc[2][3] += xv.z * wv.w;
            acc[3][0] += xv.w * wv.x; acc[3][1] += xv.w * wv.y;
            acc[3][2] += xv.w * wv.z; acc[3][3] += xv.w * wv.w;
        }
        __syncthreads();
    }

    float4 bv = *(const float4*)&bias[4 * tc];
#pragma unroll
    for (int i = 0; i < 4; i++) {
        int row = row0 + 4 * tr + i;
        float s = d_dis[row];
        float4 o;
        o.x = s * (acc[i][0] + bv.x);
        o.y = s * (acc[i][1] + bv.y);
        o.z = s * (acc[i][2] + bv.z);
        o.w = s * (acc[i][3] + bv.w);
        *(float4*)&g[row * DIM + 4 * tc] = o;
    }
}

// ---------------------------------------------------------------------------
// Fused aggregate: warp per dst node, 4-wide gather batches for MLP.
// out[dst,:] = relu(dis[dst] * (sum_{src in N(dst)} g[src,:] + g[dst,:]))
// No atomics, no accumulator buffer, no separate combine pass.
// ---------------------------------------------------------------------------
__global__ __launch_bounds__(256) void aggregate_kernel(float* __restrict__ out) {
    int dst = (blockIdx.x * blockDim.x + threadIdx.x) >> 5;  // exact: 12500*8 warps
    int lane = threadIdx.x & 31;
    const float4* g4 = (const float4*)d_g;

    int beg = __ldg(&d_rowptr[dst]);
    int end = __ldg(&d_rowptr[dst + 1]);

    float4 sum0 = make_float4(0.f, 0.f, 0.f, 0.f);
    float4 sum1 = make_float4(0.f, 0.f, 0.f, 0.f);
    float4 sum2 = make_float4(0.f, 0.f, 0.f, 0.f);
    float4 sum3 = make_float4(0.f, 0.f, 0.f, 0.f);

    int e = beg;
    for (; e + 4 <= end; e += 4) {
        int s0 = __ldg(&d_csr_src[e]);
        int s1 = __ldg(&d_csr_src[e + 1]);
        int s2 = __ldg(&d_csr_src[e + 2]);
        int s3 = __ldg(&d_csr_src[e + 3]);
        float4 v0 = __ldg(&g4[s0 * 32 + lane]);
        float4 v1 = __ldg(&g4[s1 * 32 + lane]);
        float4 v2 = __ldg(&g4[s2 * 32 + lane]);
        float4 v3 = __ldg(&g4[s3 * 32 + lane]);
        sum0.x += v0.x; sum0.y += v0.y; sum0.z += v0.z; sum0.w += v0.w;
        sum1.x += v1.x; sum1.y += v1.y; sum1.z += v1.z; sum1.w += v1.w;
        sum2.x += v2.x; sum2.y += v2.y; sum2.z += v2.z; sum2.w += v2.w;
        sum3.x += v3.x; sum3.y += v3.y; sum3.z += v3.z; sum3.w += v3.w;
    }
    for (; e < end; e++) {
        int s0 = __ldg(&d_csr_src[e]);
        float4 v0 = __ldg(&g4[s0 * 32 + lane]);
        sum0.x += v0.x; sum0.y += v0.y; sum0.z += v0.z; sum0.w += v0.w;
    }

    float4 self = __ldg(&g4[dst * 32 + lane]);
    float s = __ldg(&d_dis[dst]);
    // pairwise combine
    sum0.x += sum1.x; sum0.y += sum1.y; sum0.z += sum1.z; sum0.w += sum1.w;
    sum2.x += sum3.x; sum2.y += sum3.y; sum2.z += sum3.z; sum2.w += sum3.w;
    float4 r;
    r.x = fmaxf(s * (sum0.x + sum2.x + self.x), 0.0f);
    r.y = fmaxf(s * (sum0.y + sum2.y + self.y), 0.0f);
    r.z = fmaxf(s * (sum0.z + sum2.z + self.z), 0.0f);
    r.w = fmaxf(s * (sum0.w + sum2.w + self.w), 0.0f);
    ((float4*)out)[dst * 32 + lane] = r;
}

// ---------------------------------------------------------------------------
extern "C" void kernel_launch(void* const* d_in, const int* in_sizes, int n_in,
                              void* d_out, int out_size) {
    const float* x  = (const float*)d_in[0];
    const void*  eidx = d_in[1];
    const float* W1 = (const float*)d_in[2];
    const float* b1 = (const float*)d_in[3];
    const float* W2 = (const float*)d_in[4];
    const float* b2 = (const float*)d_in[5];
    const float* W3 = (const float*)d_in[6];
    const float* b3 = (const float*)d_in[7];
    float* out = (float*)d_out;

    // Per-call prep: dtype sniff, pack, degrees, CSR build, dis
    detect_kernel<<<1, 256>>>((const int*)eidx);
    edge_convert_kernel<<<(E_EDGES + 255) / 256, 256>>>(eidx);
    deg_zero_kernel<<<SCAN_BLOCKS, 256>>>();
    deg_count_kernel<<<(E_EDGES + 255) / 256, 256>>>();
    scan1_kernel<<<SCAN_BLOCKS, 256>>>();
    scan2_kernel<<<1, 512>>>();
    scan3_kernel<<<SCAN_BLOCKS, 256>>>();
    scatter_kernel<<<(E_EDGES + 255) / 256, 256>>>();

    float* g;     cudaGetSymbolAddress((void**)&g, d_g);
    float* xbuf;  cudaGetSymbolAddress((void**)&xbuf, d_xbuf);

    const int lin_grid = N_NODES / 32;   // 3125
    const int agg_grid = N_NODES / 8;    // warp per node, 8 warps/block = 12500

    // Layer 1
    linear_kernel<<<lin_grid, 256>>>(x, W1, b1, g);
    aggregate_kernel<<<agg_grid, 256>>>(xbuf);
    // Layer 2
    linear_kernel<<<lin_grid, 256>>>(xbuf, W2, b2, g);
    aggregate_kernel<<<agg_grid, 256>>>(xbuf);
    // Layer 3
    linear_kernel<<<lin_grid, 256>>>(xbuf, W3, b3, g);
    aggregate_kernel<<<agg_grid, 256>>>(out);
}